// round 3
// baseline (speedup 1.0000x reference)
#include <cuda_runtime.h>
#include <cuda_bf16.h>
#include <cstdint>

// Sobel gradient magnitude, zero-padded, on [B=8, C=64, H=256, W=256] fp32.
// out = sqrt(gv^2 + gh^2 + 1e-6), gv = x[i+1,j]-x[i-1,j], gh = x[i,j+1]-x[i,j-1].
//
// Round 3: 8 rows per thread. 10 front-batched float4 loads produce 8 output
// rows (1.25 vec loads per output). Horizontal neighbors via warp shuffle,
// scalar edge fixups on lanes 0/31 only, streaming stores.
//
// Layout: W4 = 64 float4 per row, H = 256 rows, plane = 2^14 float4.
// Thread t: col4 = t & 63, row-octet ro = (t>>6) & 31, plane = t >> 11.
// Warp = 32 consecutive t -> 32 consecutive col4 (never wraps a row).

static constexpr int W4 = 64;

__global__ __launch_bounds__(256)
void sobel_grad_mag_r8(const float4* __restrict__ in,
                       float4* __restrict__ out,
                       int nthreads)
{
    int t = blockIdx.x * blockDim.x + threadIdx.x;
    if (t >= nthreads) return;

    const int lane = threadIdx.x & 31;
    const int col4 = t & (W4 - 1);
    const int ro   = (t >> 6) & 31;                 // row-octet: rows 8*ro..8*ro+7
    const int i0   = ((t >> 11) << 14) | (ro << 9) | col4;

    const float4 zero = make_float4(0.f, 0.f, 0.f, 0.f);

    // 10 row vectors cover 8 output rows (front-batched for MLP)
    float4 rv[10];
    rv[0] = (ro == 0) ? zero : __ldg(&in[i0 - W4]);
    #pragma unroll
    for (int k = 0; k < 8; k++)
        rv[k + 1] = __ldg(&in[i0 + k * W4]);
    rv[9] = (ro == 31) ? zero : __ldg(&in[i0 + 8 * W4]);

    const float* sc = reinterpret_cast<const float*>(in);
    const float EPS = 1e-6f;
    const bool need_l = (lane == 0)  && (col4 != 0);
    const bool need_r = (lane == 31) && (col4 != W4 - 1);

    #pragma unroll
    for (int k = 0; k < 8; k++) {
        const float4 up = rv[k];
        const float4 c  = rv[k + 1];
        const float4 dn = rv[k + 2];

        // horizontal neighbors from adjacent lanes (same row vector)
        float l = __shfl_up_sync(0xffffffffu, c.w, 1);
        float r = __shfl_down_sync(0xffffffffu, c.x, 1);
        if (lane == 0)
            l = need_l ? sc[(size_t)(i0 + k * W4) * 4 - 1] : 0.f;
        if (lane == 31)
            r = need_r ? sc[(size_t)(i0 + k * W4) * 4 + 4] : 0.f;

        const float gv0 = dn.x - up.x;
        const float gv1 = dn.y - up.y;
        const float gv2 = dn.z - up.z;
        const float gv3 = dn.w - up.w;

        const float gh0 = c.y - l;
        const float gh1 = c.z - c.x;
        const float gh2 = c.w - c.y;
        const float gh3 = r   - c.z;

        float4 res;
        res.x = sqrtf(fmaf(gv0, gv0, fmaf(gh0, gh0, EPS)));
        res.y = sqrtf(fmaf(gv1, gv1, fmaf(gh1, gh1, EPS)));
        res.z = sqrtf(fmaf(gv2, gv2, fmaf(gh2, gh2, EPS)));
        res.w = sqrtf(fmaf(gv3, gv3, fmaf(gh3, gh3, EPS)));

        __stcs(&out[i0 + k * W4], res);
    }
}

extern "C" void kernel_launch(void* const* d_in, const int* in_sizes, int n_in,
                              void* d_out, int out_size)
{
    const float4* x = reinterpret_cast<const float4*>(d_in[0]);
    float4* o       = reinterpret_cast<float4*>(d_out);

    // total float4 outputs = out_size/4; each thread produces 8 of them
    int nthreads = out_size / 32;   // 1,048,576
    int threads  = 256;
    int blocks   = (nthreads + threads - 1) / threads;

    sobel_grad_mag_r8<<<blocks, threads>>>(x, o, nthreads);
}

// round 4
// speedup vs baseline: 1.0739x; 1.0739x over previous
#include <cuda_runtime.h>
#include <cuda_bf16.h>
#include <cstdint>

// Sobel gradient magnitude, zero-padded, on [B=8, C=64, H=256, W=256] fp32.
// out = sqrt(gv^2 + gh^2 + 1e-6), gv = x[i+1,j]-x[i-1,j], gh = x[i,j+1]-x[i,j-1].
//
// Round 4: 4 rows per thread (best redundancy/occupancy trade from R2) but with
// a ROLLING 3-vector register window instead of front-batching all 6 loads.
// Live registers drop to ~32 -> __launch_bounds__(256, 8) gives 100% theoretical
// occupancy (64 warps/SM), which supplies DRAM-latency hiding via warp count
// instead of per-thread MLP (which was inflating L1tex queue contention).
//
// Layout: W4 = 64 float4 per row, H = 256 rows, plane = 2^14 float4.
// Thread t: col4 = t & 63, row-quad rq = (t>>6) & 63, plane = t >> 12.
// Warp = 32 consecutive t -> 32 consecutive col4 (never wraps a row).

static constexpr int W4 = 64;

__global__ __launch_bounds__(256, 8)
void sobel_grad_mag_r4w(const float4* __restrict__ in,
                        float4* __restrict__ out,
                        int nthreads)
{
    int t = blockIdx.x * blockDim.x + threadIdx.x;
    if (t >= nthreads) return;

    const int lane = threadIdx.x & 31;
    const int col4 = t & (W4 - 1);
    const int rq   = (t >> 6) & 63;                 // row-quad: rows 4*rq..4*rq+3
    const int i0   = ((t >> 12) << 14) | (rq << 8) | col4;

    const float4 zero = make_float4(0.f, 0.f, 0.f, 0.f);
    const float* sc = reinterpret_cast<const float*>(in);
    const float EPS = 1e-6f;
    const bool need_l = (lane == 0)  && (col4 != 0);
    const bool need_r = (lane == 31) && (col4 != W4 - 1);

    // rolling window: up / c / dn, with dn of iteration k+1 loaded during k
    float4 up = (rq == 0) ? zero : __ldg(&in[i0 - W4]);
    float4 c  = __ldg(&in[i0]);
    float4 dn = __ldg(&in[i0 + W4]);

    #pragma unroll
    for (int k = 0; k < 4; k++) {
        // issue next row's load before this iteration's compute
        float4 nxt;
        if (k < 3) {
            nxt = (k == 2 && rq == 63) ? zero : __ldg(&in[i0 + (k + 2) * W4]);
        }

        // horizontal neighbors from adjacent lanes (same row vector)
        float l = __shfl_up_sync(0xffffffffu, c.w, 1);
        float r = __shfl_down_sync(0xffffffffu, c.x, 1);
        if (lane == 0)
            l = need_l ? sc[(size_t)(i0 + k * W4) * 4 - 1] : 0.f;
        if (lane == 31)
            r = need_r ? sc[(size_t)(i0 + k * W4) * 4 + 4] : 0.f;

        const float gv0 = dn.x - up.x;
        const float gv1 = dn.y - up.y;
        const float gv2 = dn.z - up.z;
        const float gv3 = dn.w - up.w;

        const float gh0 = c.y - l;
        const float gh1 = c.z - c.x;
        const float gh2 = c.w - c.y;
        const float gh3 = r   - c.z;

        float4 res;
        res.x = sqrtf(fmaf(gv0, gv0, fmaf(gh0, gh0, EPS)));
        res.y = sqrtf(fmaf(gv1, gv1, fmaf(gh1, gh1, EPS)));
        res.z = sqrtf(fmaf(gv2, gv2, fmaf(gh2, gh2, EPS)));
        res.w = sqrtf(fmaf(gv3, gv3, fmaf(gh3, gh3, EPS)));

        __stcs(&out[i0 + k * W4], res);

        // rotate window
        up = c;
        c  = dn;
        if (k < 3) dn = nxt;
    }
}

extern "C" void kernel_launch(void* const* d_in, const int* in_sizes, int n_in,
                              void* d_out, int out_size)
{
    const float4* x = reinterpret_cast<const float4*>(d_in[0]);
    float4* o       = reinterpret_cast<float4*>(d_out);

    // total float4 outputs = out_size/4; each thread produces 4 of them
    int nthreads = out_size / 16;   // 2,097,152
    int threads  = 256;
    int blocks   = (nthreads + threads - 1) / threads;

    sobel_grad_mag_r4w<<<blocks, threads>>>(x, o, nthreads);
}